// round 12
// baseline (speedup 1.0000x reference)
#include <cuda_runtime.h>
#include <math.h>

#define NW 22

// FINAL (= R4/R10, empirically fastest: kernel 6.85-6.91us, total 8.64us x2).
// Single-wave fused kernel: 128 blocks x 1024 threads, 8 float4 outputs/thread.
//
// Session findings (R2-R11):
//  - Kernel sits at the chip's global-write wall (~2.4 TB/s for this 16 MB
//    stream): invariant across STG/TMA/hybrid stores, grid shapes (4096x256,
//    1024x256, 128x1024, 296x1024), cache policies (__stcs), and schedules.
//  - This exact 37-reg interleaved LDS->FMUL->STG schedule reproducibly
//    measures ~0.2us faster than batched-load / abs-folded variants (34 regs).
//
// Math (validated R2-R11, rel_err 3.5e-6):
//   out[4b+2i+j] = |TA[(b>>9)&1023] * TB[b&1023]| * S[c19,c0,c1,i,j]
//   c19=b&1, c0=(b>>19)&1, c1=(b>>18)&1
//   TA indexed by c_1..c_10 (bit t = c_{10-t}),  wires 2..10
//   TB indexed by c_10..c_19 (bit t = c_{19-t}), wires 11..19
//   b_w = c_{w-1}^c_w  ->  u = v ^ (v>>1)
//
// Per thread (b = (blk<<13)+(k<<10)+t):
//   B-index = b & 1023 = t                      -> k-invariant, load once
//   sS-index uses bits 0,18,19 of b             -> k-invariant, load once
//   A-index = (b>>9)&1023, warp-uniform         -> 1 broadcast LDS per k

__global__ void __launch_bounds__(1024) qk_fused(const float* __restrict__ x,
                                                 const float* __restrict__ y,
                                                 float4* __restrict__ out) {
    __shared__ float cx[NW], sx[NW], cy[NW], sy[NW];
    __shared__ float pc[NW], ps[NW];       // pair products cx*cy, sx*sy
    __shared__ float sTA[1024], sTB[1024];
    __shared__ float4 sS[8];               // [c19][c0][c1] -> (i,j) quad
    const int t = threadIdx.x;

    if (t < NW) {
        float sxx, cxx, syy, cyy;
        __sincosf(0.5f * x[t], &sxx, &cxx);
        __sincosf(0.5f * y[t], &syy, &cyy);
        cx[t] = cxx; sx[t] = sxx; cy[t] = cyy; sy[t] = syy;
        pc[t] = cxx * cyy; ps[t] = sxx * syy;
    }
    __syncthreads();

    // Each thread fills one entry of each table.
    {
        int u = t ^ (t >> 1);
        float a = 1.0f, bb = 1.0f;
        #pragma unroll
        for (int j = 0; j < 9; ++j) {
            bool bit = (u >> j) & 1;
            a  *= bit ? ps[10 - j] : pc[10 - j];   // wires 2..10
            bb *= bit ? ps[19 - j] : pc[19 - j];   // wires 11..19
        }
        sTA[t] = a;
        sTB[t] = bb;
    }

    // S table: pre-contracted 2x2 matmul tail + abs (32 scalars).
    if (t < 32) {
        int j   =  t        & 1;
        int i   = (t >> 1)  & 1;
        int c1  = (t >> 2)  & 1;
        int c0  = (t >> 3)  & 1;
        int c19 = (t >> 4)  & 1;
        float s = 0.0f;
        #pragma unroll
        for (int k = 0; k < 2; ++k) {
            float ty = ((c19 ^ i)     ? sy[20] : cy[20])
                     * ((i   ^ k)     ? sy[21] : cy[21])
                     * ((c0  ^ k)     ? sy[0]  : cy[0])
                     * ((c0 ^ c1 ^ k) ? sy[1]  : cy[1]);
            float tx = ((c19 ^ k)     ? sx[20] : cx[20])
                     * ((k   ^ j)     ? sx[21] : cx[21])
                     * ((c0  ^ j)     ? sx[0]  : cx[0])
                     * ((c0 ^ c1 ^ j) ? sx[1]  : cx[1]);
            s += ty * tx;
        }
        reinterpret_cast<float*>(sS)[t] = fabsf(s);
    }
    __syncthreads();

    // Main loop: 8 coalesced float4 stores per thread, interleaved LDS/STG.
    const unsigned base = (unsigned)blockIdx.x << 13;
    const float B = sTB[t];                                     // b&1023 == t
    const unsigned b0 = base + (unsigned)t;
    const float4 s = sS[((b0 & 1u) << 2) | (((b0 >> 19) & 1u) << 1)
                        | ((b0 >> 18) & 1u)];                   // k-invariant
    const float Bsx = B * s.x, Bsy = B * s.y, Bsz = B * s.z, Bsw = B * s.w;

    #pragma unroll
    for (int k = 0; k < 8; ++k) {
        unsigned b = b0 + ((unsigned)k << 10);
        float A = fabsf(sTA[(b >> 9) & 1023u]);                 // warp-uniform LDS
        float4 o;
        o.x = fabsf(A * Bsx);
        o.y = fabsf(A * Bsy);
        o.z = fabsf(A * Bsz);
        o.w = fabsf(A * Bsw);
        out[b] = o;
    }
}

extern "C" void kernel_launch(void* const* d_in, const int* in_sizes, int n_in,
                              void* d_out, int out_size) {
    const float* x = (const float*)d_in[0];
    const float* y = (const float*)d_in[1];
    // 2^20 float4 outputs / (1024 threads * 8 per thread) = 128 blocks
    qk_fused<<<128, 1024>>>(x, y, (float4*)d_out);
}

// round 13
// speedup vs baseline: 1.0257x; 1.0257x over previous
#include <cuda_runtime.h>
#include <math.h>

#define NW 22

// FINAL (= R4/R10/R12, converged). Single-wave fused kernel:
// 128 blocks x 1024 threads, 8 float4 outputs/thread.
//
// Session findings (R2-R12):
//  - Kernel is pinned at the chip's global-write wall (~2.4 TB/s for this
//    16 MB output stream): invariant across STG / TMA-bulk / hybrid stores,
//    grid shapes (4096x256, 1024x256, 128x1024, 296x1024), cache policies
//    (__stcs), load batching, and abs placement.
//  - Identical binaries measure 8.64-8.93us total (run-to-run noise +-0.3us);
//    all R4-class variants are statistically indistinguishable.
//
// Math (validated R2-R12, rel_err 3.5e-6):
//   out[4b+2i+j] = |TA[(b>>9)&1023] * TB[b&1023]| * S[c19,c0,c1,i,j]
//   c19=b&1, c0=(b>>19)&1, c1=(b>>18)&1
//   TA indexed by c_1..c_10 (bit t = c_{10-t}),  wires 2..10
//   TB indexed by c_10..c_19 (bit t = c_{19-t}), wires 11..19
//   b_w = c_{w-1}^c_w  ->  u = v ^ (v>>1)
//
// Per thread (b = (blk<<13)+(k<<10)+t):
//   B-index = b & 1023 = t                      -> k-invariant, load once
//   sS-index uses bits 0,18,19 of b             -> k-invariant, load once
//   A-index = (b>>9)&1023, warp-uniform         -> 1 broadcast LDS per k

__global__ void __launch_bounds__(1024) qk_fused(const float* __restrict__ x,
                                                 const float* __restrict__ y,
                                                 float4* __restrict__ out) {
    __shared__ float cx[NW], sx[NW], cy[NW], sy[NW];
    __shared__ float pc[NW], ps[NW];       // pair products cx*cy, sx*sy
    __shared__ float sTA[1024], sTB[1024];
    __shared__ float4 sS[8];               // [c19][c0][c1] -> (i,j) quad
    const int t = threadIdx.x;

    if (t < NW) {
        float sxx, cxx, syy, cyy;
        __sincosf(0.5f * x[t], &sxx, &cxx);
        __sincosf(0.5f * y[t], &syy, &cyy);
        cx[t] = cxx; sx[t] = sxx; cy[t] = cyy; sy[t] = syy;
        pc[t] = cxx * cyy; ps[t] = sxx * syy;
    }
    __syncthreads();

    // Each thread fills one entry of each table.
    {
        int u = t ^ (t >> 1);
        float a = 1.0f, bb = 1.0f;
        #pragma unroll
        for (int j = 0; j < 9; ++j) {
            bool bit = (u >> j) & 1;
            a  *= bit ? ps[10 - j] : pc[10 - j];   // wires 2..10
            bb *= bit ? ps[19 - j] : pc[19 - j];   // wires 11..19
        }
        sTA[t] = a;
        sTB[t] = bb;
    }

    // S table: pre-contracted 2x2 matmul tail + abs (32 scalars).
    if (t < 32) {
        int j   =  t        & 1;
        int i   = (t >> 1)  & 1;
        int c1  = (t >> 2)  & 1;
        int c0  = (t >> 3)  & 1;
        int c19 = (t >> 4)  & 1;
        float s = 0.0f;
        #pragma unroll
        for (int k = 0; k < 2; ++k) {
            float ty = ((c19 ^ i)     ? sy[20] : cy[20])
                     * ((i   ^ k)     ? sy[21] : cy[21])
                     * ((c0  ^ k)     ? sy[0]  : cy[0])
                     * ((c0 ^ c1 ^ k) ? sy[1]  : cy[1]);
            float tx = ((c19 ^ k)     ? sx[20] : cx[20])
                     * ((k   ^ j)     ? sx[21] : cx[21])
                     * ((c0  ^ j)     ? sx[0]  : cx[0])
                     * ((c0 ^ c1 ^ j) ? sx[1]  : cx[1]);
            s += ty * tx;
        }
        reinterpret_cast<float*>(sS)[t] = fabsf(s);
    }
    __syncthreads();

    // Main loop: 8 coalesced float4 stores per thread, interleaved LDS/STG.
    const unsigned base = (unsigned)blockIdx.x << 13;
    const float B = sTB[t];                                     // b&1023 == t
    const unsigned b0 = base + (unsigned)t;
    const float4 s = sS[((b0 & 1u) << 2) | (((b0 >> 19) & 1u) << 1)
                        | ((b0 >> 18) & 1u)];                   // k-invariant
    const float Bsx = B * s.x, Bsy = B * s.y, Bsz = B * s.z, Bsw = B * s.w;

    #pragma unroll
    for (int k = 0; k < 8; ++k) {
        unsigned b = b0 + ((unsigned)k << 10);
        float A = fabsf(sTA[(b >> 9) & 1023u]);                 // warp-uniform LDS
        float4 o;
        o.x = fabsf(A * Bsx);
        o.y = fabsf(A * Bsy);
        o.z = fabsf(A * Bsz);
        o.w = fabsf(A * Bsw);
        out[b] = o;
    }
}

extern "C" void kernel_launch(void* const* d_in, const int* in_sizes, int n_in,
                              void* d_out, int out_size) {
    const float* x = (const float*)d_in[0];
    const float* y = (const float*)d_in[1];
    // 2^20 float4 outputs / (1024 threads * 8 per thread) = 128 blocks
    qk_fused<<<128, 1024>>>(x, y, (float4*)d_out);
}

// round 14
// speedup vs baseline: 1.0295x; 1.0037x over previous
#include <cuda_runtime.h>
#include <math.h>

#define NW 22

// R14: single untried lever vs converged R4/R10 — 256-bit stores (STG.256,
// sm_100+). Each thread writes two adjacent float4s (32B, aligned) with one
// st.global.v8.f32, halving write-request count at constant byte volume.
// Tests whether the ~2.4 TB/s wall is bytes-limited (flat) or
// request-limited (up to 2x).
//
// Math (validated R2-R13, rel_err 3.5e-6):
//   out[4b+2i+j] = |TA[(b>>9)&1023] * TB[b&1023]| * S[c19,c0,c1,i,j]
//   c19=b&1, c0=(b>>19)&1, c1=(b>>18)&1
//
// Layout: blk (7b) | chunk cc (2b) | elem = 2t or 2t+1 (11b).
//   b = (blk<<13) + (cc<<11) + 2t (+1)
//   B-indices (2t)&1023, (2t+1)&1023   : chunk-invariant
//   S quads: bits 18,19 from blk only; c19 = elem parity -> two quads, fixed
//   A-index (b>>9)&1023: shared by the pair, warp-uniform, varies per chunk

__global__ void __launch_bounds__(1024) qk_fused(const float* __restrict__ x,
                                                 const float* __restrict__ y,
                                                 float4* __restrict__ out) {
    __shared__ float cx[NW], sx[NW], cy[NW], sy[NW];
    __shared__ float pc[NW], ps[NW];
    __shared__ float sTA[1024], sTB[1024];
    __shared__ float4 sS[8];
    const int t = threadIdx.x;

    if (t < NW) {
        float sxx, cxx, syy, cyy;
        __sincosf(0.5f * x[t], &sxx, &cxx);
        __sincosf(0.5f * y[t], &syy, &cyy);
        cx[t] = cxx; sx[t] = sxx; cy[t] = cyy; sy[t] = syy;
        pc[t] = cxx * cyy; ps[t] = sxx * syy;
    }
    __syncthreads();

    {
        int u = t ^ (t >> 1);
        float a = 1.0f, bb = 1.0f;
        #pragma unroll
        for (int j = 0; j < 9; ++j) {
            bool bit = (u >> j) & 1;
            a  *= bit ? ps[10 - j] : pc[10 - j];   // wires 2..10
            bb *= bit ? ps[19 - j] : pc[19 - j];   // wires 11..19
        }
        sTA[t] = a;
        sTB[t] = bb;
    }

    if (t < 32) {
        int j   =  t        & 1;
        int i   = (t >> 1)  & 1;
        int c1  = (t >> 2)  & 1;
        int c0  = (t >> 3)  & 1;
        int c19 = (t >> 4)  & 1;
        float s = 0.0f;
        #pragma unroll
        for (int k = 0; k < 2; ++k) {
            float ty = ((c19 ^ i)     ? sy[20] : cy[20])
                     * ((i   ^ k)     ? sy[21] : cy[21])
                     * ((c0  ^ k)     ? sy[0]  : cy[0])
                     * ((c0 ^ c1 ^ k) ? sy[1]  : cy[1]);
            float tx = ((c19 ^ k)     ? sx[20] : cx[20])
                     * ((k   ^ j)     ? sx[21] : cx[21])
                     * ((c0  ^ j)     ? sx[0]  : cx[0])
                     * ((c0 ^ c1 ^ j) ? sx[1]  : cx[1]);
            s += ty * tx;
        }
        reinterpret_cast<float*>(sS)[t] = fabsf(s);
    }
    __syncthreads();

    const unsigned base = (unsigned)blockIdx.x << 13;     // block's first b
    const unsigned e0 = 2u * (unsigned)t;                 // even element
    const float B0 = fabsf(sTB[e0 & 1023u]);
    const float B1 = fabsf(sTB[(e0 + 1u) & 1023u]);
    // S quads: bits 18,19 of b depend only on blk; c19 = parity.
    const unsigned hi = ((((base >> 19) & 1u) << 1) | ((base >> 18) & 1u));
    const float4 sE = sS[hi];            // c19 = 0
    const float4 sO = sS[4u | hi];       // c19 = 1
    const float E0x = B0 * sE.x, E0y = B0 * sE.y, E0z = B0 * sE.z, E0w = B0 * sE.w;
    const float O1x = B1 * sO.x, O1y = B1 * sO.y, O1z = B1 * sO.z, O1w = B1 * sO.w;

    #pragma unroll
    for (int cc = 0; cc < 4; ++cc) {
        unsigned b = base + ((unsigned)cc << 11) + e0;
        float A = fabsf(sTA[(b >> 9) & 1023u]);           // shared by the pair
        float v0 = A * E0x, v1 = A * E0y, v2 = A * E0z, v3 = A * E0w;
        float v4 = A * O1x, v5 = A * O1y, v6 = A * O1z, v7 = A * O1w;
        float4* p = &out[b];                              // 32B-aligned (b even)
        asm volatile(
            "st.global.v8.f32 [%0], {%1, %2, %3, %4, %5, %6, %7, %8};"
            :: "l"(p),
               "f"(v0), "f"(v1), "f"(v2), "f"(v3),
               "f"(v4), "f"(v5), "f"(v6), "f"(v7)
            : "memory");
    }
}

extern "C" void kernel_launch(void* const* d_in, const int* in_sizes, int n_in,
                              void* d_out, int out_size) {
    const float* x = (const float*)d_in[0];
    const float* y = (const float*)d_in[1];
    // 2^20 float4 outputs / (1024 threads * 2 float4 * 4 chunks) = 128 blocks
    qk_fused<<<128, 1024>>>(x, y, (float4*)d_out);
}